// round 1
// baseline (speedup 1.0000x reference)
#include <cuda_runtime.h>
#include <math.h>

// ---------------- problem constants ----------------
#define Dm      1024
#define Hh      16
#define DHd     64
#define Ff      4096
#define Ee      8
#define TOPK    2
#define Bbat    2
#define Sseq    2048
#define Ntok    4096            // Bbat*Sseq
#define NKCAP   16384           // padded expert-row capacity (>= 8192 + padding)

// ---------------- device scratch (static; no allocs) ----------------
__device__ float g_Q [Ntok * Dm];
__device__ float g_K [Ntok * Dm];
__device__ float g_V [Ntok * Dm];
__device__ float g_AT[Ntok * Dm];
__device__ float g_PR[Ntok * Dm];
__device__ float g_X1[Ntok * Dm];
__device__ float g_X2[Ntok * Dm];
__device__ float g_SC[(size_t)Bbat * Hh * Sseq * Sseq];   // 512 MB attention scores

__device__ float g_XG[(size_t)NKCAP * Dm];
__device__ float g_HB[(size_t)NKCAP * Ff];
__device__ float g_YG[(size_t)NKCAP * Dm];
__device__ float g_MO[Ntok * Dm];

__device__ int   g_tok_e[Ntok * TOPK];
__device__ float g_tok_g[Ntok * TOPK];
__device__ int   g_cnt[Ee];
__device__ int   g_cur[Ee];
__device__ int   g_off[Ee + 1];
__device__ int   g_row_tok[NKCAP];
__device__ float g_row_gate[NKCAP];
__device__ float g_auxp[Ntok * Ee];
__device__ int   g_auxi[Ntok * TOPK];

// ---------------- generic 128x128x16 fp32 GEMM tile ----------------
__device__ __forceinline__ void gemm_tile_128(
    const float* __restrict__ A, int lda,
    const float* __restrict__ Bm, int ldb,
    const float* __restrict__ bias,
    float* __restrict__ C, int ldc,
    int M, int Kd, int bm, int bn, int relu)
{
    __shared__ float As[16][128];
    __shared__ float Bs[16][132];
    const int tid = threadIdx.x;
    float acc[8][8];
#pragma unroll
    for (int i = 0; i < 8; i++)
#pragma unroll
        for (int j = 0; j < 8; j++) acc[i][j] = 0.f;

    const int mr = (tid >> 4) << 3;   // 0..120
    const int nc = (tid & 15) << 3;   // 0..120

    for (int k0 = 0; k0 < Kd; k0 += 16) {
        // A tile: 128 rows x 16 cols -> transposed into As[k][m]
#pragma unroll
        for (int i = 0; i < 2; i++) {
            int idx = tid * 2 + i;            // 0..511 float4 units
            int r = idx >> 2;
            int c = (idx & 3) << 2;
            float4 v = make_float4(0.f, 0.f, 0.f, 0.f);
            int gr = bm + r;
            if (gr < M)
                v = *reinterpret_cast<const float4*>(A + (size_t)gr * lda + k0 + c);
            As[c + 0][r] = v.x; As[c + 1][r] = v.y;
            As[c + 2][r] = v.z; As[c + 3][r] = v.w;
        }
        // B tile: 16 rows x 128 cols
#pragma unroll
        for (int i = 0; i < 2; i++) {
            int idx = tid * 2 + i;
            int r = idx >> 5;                 // 0..15
            int c = (idx & 31) << 2;          // 0..124
            float4 v = *reinterpret_cast<const float4*>(Bm + (size_t)(k0 + r) * ldb + bn + c);
            Bs[r][c] = v.x; Bs[r][c + 1] = v.y;
            Bs[r][c + 2] = v.z; Bs[r][c + 3] = v.w;
        }
        __syncthreads();
#pragma unroll
        for (int k = 0; k < 16; k++) {
            float a[8], b[8];
#pragma unroll
            for (int i = 0; i < 8; i++) a[i] = As[k][mr + i];
#pragma unroll
            for (int j = 0; j < 8; j++) b[j] = Bs[k][nc + j];
#pragma unroll
            for (int i = 0; i < 8; i++)
#pragma unroll
                for (int j = 0; j < 8; j++)
                    acc[i][j] += a[i] * b[j];
        }
        __syncthreads();
    }
#pragma unroll
    for (int i = 0; i < 8; i++) {
        int gr = bm + mr + i;
        if (gr >= M) continue;
#pragma unroll
        for (int j = 0; j < 8; j++) {
            float v = acc[i][j] + bias[bn + nc + j];
            if (relu) v = fmaxf(v, 0.f);
            C[(size_t)gr * ldc + bn + nc + j] = v;
        }
    }
}

__global__ void k_sgemm(const float* __restrict__ A, int lda,
                        const float* __restrict__ Bm, int ldb,
                        const float* __restrict__ bias,
                        float* __restrict__ C, int ldc,
                        int M, int Kd, int relu)
{
    gemm_tile_128(A, lda, Bm, ldb, bias, C, ldc, M, Kd,
                  blockIdx.x * 128, blockIdx.y * 128, relu);
}

// MoE grouped GEMM: blockIdx.z = expert; M comes from device-computed counts.
__global__ void k_moe_gemm(const float* __restrict__ Abase,
                           const float* __restrict__ Wbase,
                           const float* __restrict__ bbase,
                           float* __restrict__ Cbase,
                           int Kd, int Nn, int relu)
{
    int e = blockIdx.z;
    int cnt = g_cnt[e];
    int bm = blockIdx.x * 128;
    if (bm >= cnt) return;
    int off = g_off[e];
    gemm_tile_128(Abase + (size_t)off * Kd, Kd,
                  Wbase + (size_t)e * Kd * Nn, Nn,
                  bbase + (size_t)e * Nn,
                  Cbase + (size_t)off * Nn, Nn,
                  cnt, Kd, bm, blockIdx.y * 128, relu);
}

// ---------------- attention ----------------
__global__ void k_attn_scores(const float* __restrict__ Qb,
                              const float* __restrict__ Kb,
                              float* __restrict__ SC)
{
    int bh = blockIdx.z;
    int b = bh >> 4, h = bh & 15;
    int q0 = blockIdx.x * 64, k0 = blockIdx.y * 64;
    __shared__ float Qs[64][65], Ks[64][65];
    int tid = threadIdx.x;
    const float* Qp = Qb + (size_t)b * Sseq * Dm + h * DHd;
    const float* Kp = Kb + (size_t)b * Sseq * Dm + h * DHd;
#pragma unroll
    for (int i = 0; i < 4; i++) {
        int idx = tid + i * 256;              // 0..1023 float4 units
        int r = idx >> 4;
        int c = (idx & 15) << 2;
        float4 q = *reinterpret_cast<const float4*>(Qp + (size_t)(q0 + r) * Dm + c);
        Qs[r][c] = q.x; Qs[r][c + 1] = q.y; Qs[r][c + 2] = q.z; Qs[r][c + 3] = q.w;
        float4 kv = *reinterpret_cast<const float4*>(Kp + (size_t)(k0 + r) * Dm + c);
        Ks[r][c] = kv.x; Ks[r][c + 1] = kv.y; Ks[r][c + 2] = kv.z; Ks[r][c + 3] = kv.w;
    }
    __syncthreads();
    int r0 = (tid >> 4) << 2, c0 = (tid & 15) << 2;
    float acc[4][4];
#pragma unroll
    for (int i = 0; i < 4; i++)
#pragma unroll
        for (int j = 0; j < 4; j++) acc[i][j] = 0.f;
#pragma unroll
    for (int k = 0; k < 64; k++) {
        float a[4], bv[4];
#pragma unroll
        for (int i = 0; i < 4; i++) a[i] = Qs[r0 + i][k];
#pragma unroll
        for (int j = 0; j < 4; j++) bv[j] = Ks[c0 + j][k];
#pragma unroll
        for (int i = 0; i < 4; i++)
#pragma unroll
            for (int j = 0; j < 4; j++)
                acc[i][j] += a[i] * bv[j];
    }
    float* out = SC + (size_t)bh * Sseq * Sseq;
#pragma unroll
    for (int i = 0; i < 4; i++)
#pragma unroll
        for (int j = 0; j < 4; j++)
            out[(size_t)(q0 + r0 + i) * Sseq + k0 + c0 + j] = acc[i][j] * 0.125f;
}

__global__ void k_softmax(float* __restrict__ SC)
{
    size_t row = blockIdx.x;
    float* p = SC + row * Sseq;
    int tid = threadIdx.x;
    float v[8];
    float mx = -1e30f;
#pragma unroll
    for (int i = 0; i < 8; i++) { v[i] = p[tid + i * 256]; mx = fmaxf(mx, v[i]); }
    __shared__ float red[256];
    red[tid] = mx; __syncthreads();
    for (int st = 128; st > 0; st >>= 1) {
        if (tid < st) red[tid] = fmaxf(red[tid], red[tid + st]);
        __syncthreads();
    }
    mx = red[0]; __syncthreads();
    float sm = 0.f;
#pragma unroll
    for (int i = 0; i < 8; i++) { v[i] = expf(v[i] - mx); sm += v[i]; }
    red[tid] = sm; __syncthreads();
    for (int st = 128; st > 0; st >>= 1) {
        if (tid < st) red[tid] += red[tid + st];
        __syncthreads();
    }
    float inv = 1.f / red[0];
#pragma unroll
    for (int i = 0; i < 8; i++) p[tid + i * 256] = v[i] * inv;
}

__global__ void k_attn_av(const float* __restrict__ SC,
                          const float* __restrict__ Vb,
                          float* __restrict__ AT)
{
    int bh = blockIdx.y;
    int b = bh >> 4, h = bh & 15;
    int q0 = blockIdx.x * 64;
    __shared__ float Ps[64][65], Vs[64][65];
    int tid = threadIdx.x;
    const float* Pp = SC + (size_t)bh * Sseq * Sseq;
    const float* Vp = Vb + (size_t)b * Sseq * Dm + h * DHd;
    int r0 = (tid >> 4) << 2, c0 = (tid & 15) << 2;
    float acc[4][4];
#pragma unroll
    for (int i = 0; i < 4; i++)
#pragma unroll
        for (int j = 0; j < 4; j++) acc[i][j] = 0.f;

    for (int kt = 0; kt < Sseq; kt += 64) {
#pragma unroll
        for (int i = 0; i < 4; i++) {
            int idx = tid + i * 256;
            int r = idx >> 4;
            int c = (idx & 15) << 2;
            float4 pv = *reinterpret_cast<const float4*>(Pp + (size_t)(q0 + r) * Sseq + kt + c);
            Ps[r][c] = pv.x; Ps[r][c + 1] = pv.y; Ps[r][c + 2] = pv.z; Ps[r][c + 3] = pv.w;
            float4 vv = *reinterpret_cast<const float4*>(Vp + (size_t)(kt + r) * Dm + c);
            Vs[r][c] = vv.x; Vs[r][c + 1] = vv.y; Vs[r][c + 2] = vv.z; Vs[r][c + 3] = vv.w;
        }
        __syncthreads();
#pragma unroll
        for (int k = 0; k < 64; k++) {
            float a[4], bv[4];
#pragma unroll
            for (int i = 0; i < 4; i++) a[i] = Ps[r0 + i][k];
#pragma unroll
            for (int j = 0; j < 4; j++) bv[j] = Vs[k][c0 + j];
#pragma unroll
            for (int i = 0; i < 4; i++)
#pragma unroll
                for (int j = 0; j < 4; j++)
                    acc[i][j] += a[i] * bv[j];
        }
        __syncthreads();
    }
#pragma unroll
    for (int i = 0; i < 4; i++)
#pragma unroll
        for (int j = 0; j < 4; j++)
            AT[(size_t)(b * Sseq + q0 + r0 + i) * Dm + h * DHd + c0 + j] = acc[i][j];
}

// ---------------- layernorm(residual) ----------------
__global__ void k_ln_res(const float* __restrict__ X, const float* __restrict__ R,
                         const float* __restrict__ gw, const float* __restrict__ bw,
                         float* __restrict__ O)
{
    int t = blockIdx.x, tid = threadIdx.x;
    const float* xp = X + (size_t)t * Dm;
    const float* rp = R + (size_t)t * Dm;
    float v[4]; float s = 0.f;
#pragma unroll
    for (int i = 0; i < 4; i++) { int d = tid + i * 256; v[i] = xp[d] + rp[d]; s += v[i]; }
    __shared__ float red[256];
    red[tid] = s; __syncthreads();
    for (int st = 128; st > 0; st >>= 1) {
        if (tid < st) red[tid] += red[tid + st];
        __syncthreads();
    }
    float mean = red[0] * (1.f / Dm);
    __syncthreads();
    float s2 = 0.f;
#pragma unroll
    for (int i = 0; i < 4; i++) { float dd = v[i] - mean; s2 += dd * dd; }
    red[tid] = s2; __syncthreads();
    for (int st = 128; st > 0; st >>= 1) {
        if (tid < st) red[tid] += red[tid + st];
        __syncthreads();
    }
    float rstd = rsqrtf(red[0] * (1.f / Dm) + 1e-5f);
    float* op = O + (size_t)t * Dm;
#pragma unroll
    for (int i = 0; i < 4; i++) {
        int d = tid + i * 256;
        op[d] = (v[i] - mean) * rstd * gw[d] + bw[d];
    }
}

// ---------------- MoE routing / dispatch ----------------
__global__ void k_moe_init()
{
    int tid = threadIdx.x;
    if (tid < Ee) { g_cnt[tid] = 0; g_cur[tid] = 0; }
    for (int i = tid; i < NKCAP; i += 256) g_row_tok[i] = -1;
}

__global__ void k_router(const float* __restrict__ X,
                         const float* __restrict__ rw,
                         const float* __restrict__ rb,
                         int mode)   // 0 = dispatch pass, 1 = aux pass
{
    int t = blockIdx.x, tid = threadIdx.x;
    const float* xp = X + (size_t)t * Dm;
    float loc[Ee];
#pragma unroll
    for (int e = 0; e < Ee; e++) loc[e] = 0.f;
    for (int d = tid; d < Dm; d += 256) {
        float xv = xp[d];
#pragma unroll
        for (int e = 0; e < Ee; e++) loc[e] += xv * rw[d * Ee + e];
    }
    __shared__ float red[256 * Ee];
#pragma unroll
    for (int e = 0; e < Ee; e++) red[tid * Ee + e] = loc[e];
    __syncthreads();
    for (int st = 128; st > 0; st >>= 1) {
        if (tid < st)
#pragma unroll
            for (int e = 0; e < Ee; e++)
                red[tid * Ee + e] += red[(tid + st) * Ee + e];
        __syncthreads();
    }
    if (tid == 0) {
        float lg[Ee], mx = -1e30f;
#pragma unroll
        for (int e = 0; e < Ee; e++) { lg[e] = red[e] + rb[e]; mx = fmaxf(mx, lg[e]); }
        float sm = 0.f;
#pragma unroll
        for (int e = 0; e < Ee; e++) { lg[e] = expf(lg[e] - mx); sm += lg[e]; }
        float inv = 1.f / sm;
#pragma unroll
        for (int e = 0; e < Ee; e++) lg[e] *= inv;
        int e0 = 0;
#pragma unroll
        for (int e = 1; e < Ee; e++) if (lg[e] > lg[e0]) e0 = e;
        int e1 = -1;
#pragma unroll
        for (int e = 0; e < Ee; e++)
            if (e != e0 && (e1 < 0 || lg[e] > lg[e1])) e1 = e;
        if (mode == 0) {
            float g0 = lg[e0], g1 = lg[e1], gs = g0 + g1;
            g_tok_e[t * 2] = e0;  g_tok_e[t * 2 + 1] = e1;
            g_tok_g[t * 2] = g0 / gs; g_tok_g[t * 2 + 1] = g1 / gs;
            atomicAdd(&g_cnt[e0], 1); atomicAdd(&g_cnt[e1], 1);
        } else {
#pragma unroll
            for (int e = 0; e < Ee; e++) g_auxp[t * Ee + e] = lg[e];
            g_auxi[t * 2] = e0; g_auxi[t * 2 + 1] = e1;
        }
    }
}

__global__ void k_offsets()
{
    if (threadIdx.x == 0) {
        int acc = 0;
        for (int e = 0; e < Ee; e++) {
            g_off[e] = acc;
            acc += ((g_cnt[e] + 127) >> 7) << 7;   // pad to 128-row tiles
        }
        g_off[Ee] = acc;
    }
}

__global__ void k_gather(const float* __restrict__ X)
{
    int t = blockIdx.x, tid = threadIdx.x;
    __shared__ int spos[TOPK];
    if (tid == 0) {
#pragma unroll
        for (int k = 0; k < TOPK; k++) {
            int e = g_tok_e[t * 2 + k];
            int p = g_off[e] + atomicAdd(&g_cur[e], 1);
            spos[k] = p;
            g_row_tok[p] = t;
            g_row_gate[p] = g_tok_g[t * 2 + k];
        }
    }
    __syncthreads();
    const float4* src = reinterpret_cast<const float4*>(X + (size_t)t * Dm);
#pragma unroll
    for (int k = 0; k < TOPK; k++) {
        float4* dst = reinterpret_cast<float4*>(g_XG + (size_t)spos[k] * Dm);
        dst[tid] = src[tid];
    }
}

__global__ void k_zero_mo()
{
    int t = blockIdx.x, tid = threadIdx.x;
    float4 z = make_float4(0.f, 0.f, 0.f, 0.f);
    reinterpret_cast<float4*>(g_MO + (size_t)t * Dm)[tid] = z;
}

__global__ void k_scatter()
{
    int p = blockIdx.x;
    int t = g_row_tok[p];
    if (t < 0) return;
    float gt = g_row_gate[p];
    int tid = threadIdx.x;
    for (int d = tid; d < Dm; d += 256)
        atomicAdd(&g_MO[(size_t)t * Dm + d], gt * g_YG[(size_t)p * Dm + d]);
}

__global__ void k_aux_final(float* __restrict__ out)
{
    int tid = threadIdx.x;
    float imp[Ee];
#pragma unroll
    for (int e = 0; e < Ee; e++) imp[e] = 0.f;
    for (int t = tid; t < Ntok; t += 256)
#pragma unroll
        for (int e = 0; e < Ee; e++) imp[e] += g_auxp[t * Ee + e];
    float ld[Ee];
#pragma unroll
    for (int e = 0; e < Ee; e++) ld[e] = 0.f;
    for (int i = tid; i < Ntok * TOPK; i += 256) ld[g_auxi[i]] += 1.f;

    __shared__ float red[256 * Ee];
    __shared__ float simp[Ee];
#pragma unroll
    for (int e = 0; e < Ee; e++) red[tid * Ee + e] = imp[e];
    __syncthreads();
    for (int st = 128; st > 0; st >>= 1) {
        if (tid < st)
#pragma unroll
            for (int e = 0; e < Ee; e++)
                red[tid * Ee + e] += red[(tid + st) * Ee + e];
        __syncthreads();
    }
    if (tid == 0)
#pragma unroll
        for (int e = 0; e < Ee; e++) simp[e] = red[e];
    __syncthreads();
#pragma unroll
    for (int e = 0; e < Ee; e++) red[tid * Ee + e] = ld[e];
    __syncthreads();
    for (int st = 128; st > 0; st >>= 1) {
        if (tid < st)
#pragma unroll
            for (int e = 0; e < Ee; e++)
                red[tid * Ee + e] += red[(tid + st) * Ee + e];
        __syncthreads();
    }
    if (tid == 0) {
        float aux = 0.f;
#pragma unroll
        for (int e = 0; e < Ee; e++)
            aux += (simp[e] / (float)Ntok) * (red[e] / (float)(Ntok * TOPK));
        out[0] = (float)Ee * aux;
    }
}

// ---------------- host orchestration ----------------
extern "C" void kernel_launch(void* const* d_in, const int* in_sizes, int n_in,
                              void* d_out, int out_size)
{
    (void)in_sizes; (void)n_in;
    const float* x     = (const float*)d_in[0];
    const float* enc   = (const float*)d_in[1];
    const float* sa_wq = (const float*)d_in[2];
    const float* sa_bq = (const float*)d_in[3];
    const float* sa_wk = (const float*)d_in[4];
    const float* sa_bk = (const float*)d_in[5];
    const float* sa_wv = (const float*)d_in[6];
    const float* sa_bv = (const float*)d_in[7];
    const float* sa_wo = (const float*)d_in[8];
    const float* sa_bo = (const float*)d_in[9];
    const float* ca_wq = (const float*)d_in[10];
    const float* ca_bq = (const float*)d_in[11];
    const float* ca_wk = (const float*)d_in[12];
    const float* ca_bk = (const float*)d_in[13];
    const float* ca_wv = (const float*)d_in[14];
    const float* ca_bv = (const float*)d_in[15];
    const float* ca_wo = (const float*)d_in[16];
    const float* ca_bo = (const float*)d_in[17];
    const float* n1_g  = (const float*)d_in[18];
    const float* n1_b  = (const float*)d_in[19];
    const float* n2_g  = (const float*)d_in[20];
    const float* n2_b  = (const float*)d_in[21];
    const float* n3_g  = (const float*)d_in[22];
    const float* n3_b  = (const float*)d_in[23];
    const float* r_w   = (const float*)d_in[24];
    const float* r_b   = (const float*)d_in[25];
    const float* e_w1  = (const float*)d_in[26];
    const float* e_b1  = (const float*)d_in[27];
    const float* e_w2  = (const float*)d_in[28];
    const float* e_b2  = (const float*)d_in[29];

    void *pQ, *pK, *pV, *pAT, *pPR, *pX1, *pX2, *pSC, *pXG, *pHB, *pYG, *pMO;
    cudaGetSymbolAddress(&pQ,  g_Q);
    cudaGetSymbolAddress(&pK,  g_K);
    cudaGetSymbolAddress(&pV,  g_V);
    cudaGetSymbolAddress(&pAT, g_AT);
    cudaGetSymbolAddress(&pPR, g_PR);
    cudaGetSymbolAddress(&pX1, g_X1);
    cudaGetSymbolAddress(&pX2, g_X2);
    cudaGetSymbolAddress(&pSC, g_SC);
    cudaGetSymbolAddress(&pXG, g_XG);
    cudaGetSymbolAddress(&pHB, g_HB);
    cudaGetSymbolAddress(&pYG, g_YG);
    cudaGetSymbolAddress(&pMO, g_MO);
    float* Q  = (float*)pQ;  float* K  = (float*)pK;  float* V  = (float*)pV;
    float* AT = (float*)pAT; float* PR = (float*)pPR;
    float* X1 = (float*)pX1; float* X2 = (float*)pX2;
    float* SC = (float*)pSC;
    float* XG = (float*)pXG; float* HB = (float*)pHB; float* YG = (float*)pYG;
    float* out = (float*)d_out;

    dim3 blk(256);
    dim3 gProj(Ntok / 128, Dm / 128);          // 32 x 8
    dim3 gScore(Sseq / 64, Sseq / 64, Bbat * Hh);
    dim3 gAV(Sseq / 64, Bbat * Hh);

    // ---- self attention ----
    k_sgemm<<<gProj, blk>>>(x, Dm, sa_wq, Dm, sa_bq, Q, Dm, Ntok, Dm, 0);
    k_sgemm<<<gProj, blk>>>(x, Dm, sa_wk, Dm, sa_bk, K, Dm, Ntok, Dm, 0);
    k_sgemm<<<gProj, blk>>>(x, Dm, sa_wv, Dm, sa_bv, V, Dm, Ntok, Dm, 0);
    k_attn_scores<<<gScore, blk>>>(Q, K, SC);
    k_softmax<<<Bbat * Hh * Sseq, blk>>>(SC);
    k_attn_av<<<gAV, blk>>>(SC, V, AT);
    k_sgemm<<<gProj, blk>>>(AT, Dm, sa_wo, Dm, sa_bo, PR, Dm, Ntok, Dm, 0);
    k_ln_res<<<Ntok, blk>>>(x, PR, n1_g, n1_b, X1);

    // ---- cross attention ----
    k_sgemm<<<gProj, blk>>>(X1,  Dm, ca_wq, Dm, ca_bq, Q, Dm, Ntok, Dm, 0);
    k_sgemm<<<gProj, blk>>>(enc, Dm, ca_wk, Dm, ca_bk, K, Dm, Ntok, Dm, 0);
    k_sgemm<<<gProj, blk>>>(enc, Dm, ca_wv, Dm, ca_bv, V, Dm, Ntok, Dm, 0);
    k_attn_scores<<<gScore, blk>>>(Q, K, SC);
    k_softmax<<<Bbat * Hh * Sseq, blk>>>(SC);
    k_attn_av<<<gAV, blk>>>(SC, V, AT);
    k_sgemm<<<gProj, blk>>>(AT, Dm, ca_wo, Dm, ca_bo, PR, Dm, Ntok, Dm, 0);
    k_ln_res<<<Ntok, blk>>>(X1, PR, n2_g, n2_b, X2);

    // ---- MoE (sparse top-2 dispatch) ----
    k_moe_init<<<1, blk>>>();
    k_router<<<Ntok, blk>>>(X2, r_w, r_b, 0);
    k_offsets<<<1, 1>>>();
    k_gather<<<Ntok, blk>>>(X2);
    k_moe_gemm<<<dim3(Ntok / 128, Ff / 128, Ee), blk>>>(XG, e_w1, e_b1, HB, Dm, Ff, 1);
    k_moe_gemm<<<dim3(Ntok / 128, Dm / 128, Ee), blk>>>(HB, e_w2, e_b2, YG, Ff, Dm, 0);
    k_zero_mo<<<Ntok, blk>>>();
    k_scatter<<<NKCAP, blk>>>();
    k_ln_res<<<Ntok, blk>>>(X2, (float*)pMO, n3_g, n3_b, out);

    // ---- aux loss (router recompute on OUTPUT, per reference) ----
    if (out_size > Ntok * Dm) {
        k_router<<<Ntok, blk>>>(out, r_w, r_b, 1);
        k_aux_final<<<1, blk>>>(out + (out_size - 1));
    }
}

// round 2
// speedup vs baseline: 2.6273x; 2.6273x over previous
#include <cuda_runtime.h>
#include <math.h>

// ---------------- problem constants ----------------
#define Dm      1024
#define Hh      16
#define DHd     64
#define Ff      4096
#define Ee      8
#define TOPK    2
#define Bbat    2
#define Sseq    2048
#define Ntok    4096
#define NKCAP   16384

// ---------------- device scratch ----------------
__device__ float g_Q [Ntok * Dm];
__device__ float g_K [Ntok * Dm];
__device__ float g_V [Ntok * Dm];
__device__ float g_AT[Ntok * Dm];
__device__ float g_PR[Ntok * Dm];
__device__ float g_X1[Ntok * Dm];
__device__ float g_X2[Ntok * Dm];
__device__ float g_SC[(size_t)Bbat * Hh * Sseq * Sseq];

__device__ float g_XG[(size_t)NKCAP * Dm];
__device__ float g_HB[(size_t)NKCAP * Ff];
__device__ float g_YG[(size_t)NKCAP * Dm];
__device__ float g_MO[Ntok * Dm];

__device__ int   g_tok_e[Ntok * TOPK];
__device__ float g_tok_g[Ntok * TOPK];
__device__ int   g_cnt[Ee];
__device__ int   g_cur[Ee];
__device__ int   g_off[Ee + 1];
__device__ int   g_row_tok[NKCAP];
__device__ float g_row_gate[NKCAP];
__device__ float g_auxp[Ntok * Ee];
__device__ int   g_auxi[Ntok * TOPK];

// ---------------- tf32 helpers ----------------
__device__ __forceinline__ unsigned f2tf(float f) {
    unsigned r;
    asm("cvt.rna.tf32.f32 %0, %1;" : "=r"(r) : "f"(f));
    return r;
}

__device__ __forceinline__ void mma_tf32(float* c, const unsigned* a, const unsigned* b) {
    asm volatile(
        "mma.sync.aligned.m16n8k8.row.col.f32.tf32.tf32.f32 "
        "{%0,%1,%2,%3},{%4,%5,%6,%7},{%8,%9},{%0,%1,%2,%3};\n"
        : "+f"(c[0]), "+f"(c[1]), "+f"(c[2]), "+f"(c[3])
        : "r"(a[0]), "r"(a[1]), "r"(a[2]), "r"(a[3]), "r"(b[0]), "r"(b[1]));
}

// ---------------- generic tensor-core GEMM tile ----------------
// BLAYOUT 0: B given row-major [k][n]  (weights, V)
// BLAYOUT 1: B given row-major [n][k]  (K for Q*K^T)
template<int BLAYOUT, int BN>
__device__ __forceinline__ void mma_gemm_tile(
    const float* __restrict__ A, int lda,
    const float* __restrict__ Bg, int ldb,
    const float* __restrict__ bias,
    float* __restrict__ C, int ldc,
    int M, int Kd, int bm, int bn, int relu, float scale)
{
    constexpr int BM = 128, BK = 32;
    constexpr int WC = (BN == 128) ? 4 : 2;      // warp cols
    constexpr int WM = (BN == 128) ? 64 : 32;    // warp tile M
    constexpr int WN = 32;                        // warp tile N
    constexpr int MT = WM / 16;                   // 4 or 2
    constexpr int NT = WN / 8;                    // 4
    constexpr int AP = BK + 4;                    // 36
    constexpr int BP = (BLAYOUT == 0) ? (BN + 8) : (BK + 4);
    constexpr int BROWS = (BLAYOUT == 0) ? BK : BN;
    constexpr int BITERS = (BK * BN) / 1024;      // float4 loads per thread for B

    __shared__ unsigned As[BM * AP];
    __shared__ unsigned Bs[BROWS * BP];

    const int tid  = threadIdx.x;
    const int lane = tid & 31;
    const int wid  = tid >> 5;
    const int wm = (wid / WC) * WM;
    const int wn = (wid % WC) * WN;
    const int g  = lane >> 2;
    const int tg = lane & 3;

    float acc[MT][NT][4];
#pragma unroll
    for (int i = 0; i < MT; i++)
#pragma unroll
        for (int j = 0; j < NT; j++)
#pragma unroll
            for (int q = 0; q < 4; q++) acc[i][j][q] = 0.f;

    float4 ra[4], rb[BITERS];
    const int ktiles = Kd / BK;

    // ---- prologue: load k-tile 0 into regs, store to smem ----
#pragma unroll
    for (int i = 0; i < 4; i++) {
        int idx = tid + i * 256; int r = idx >> 3, c = (idx & 7) << 2;
        int grow = bm + r;
        ra[i] = (grow < M) ? *(const float4*)(A + (size_t)grow * lda + c)
                           : make_float4(0.f, 0.f, 0.f, 0.f);
    }
    if (BLAYOUT == 0) {
#pragma unroll
        for (int i = 0; i < BITERS; i++) {
            int idx = tid + i * 256;
            int r = (BN == 128) ? (idx >> 5) : (idx >> 4);
            int c = (BN == 128) ? ((idx & 31) << 2) : ((idx & 15) << 2);
            rb[i] = *(const float4*)(Bg + (size_t)r * ldb + bn + c);
        }
    } else {
#pragma unroll
        for (int i = 0; i < BITERS; i++) {
            int idx = tid + i * 256; int r = idx >> 3, c = (idx & 7) << 2;
            rb[i] = *(const float4*)(Bg + (size_t)(bn + r) * ldb + c);
        }
    }
#pragma unroll
    for (int i = 0; i < 4; i++) {
        int idx = tid + i * 256; int r = idx >> 3, c = (idx & 7) << 2;
        unsigned* p = &As[r * AP + c];
        p[0] = f2tf(ra[i].x); p[1] = f2tf(ra[i].y);
        p[2] = f2tf(ra[i].z); p[3] = f2tf(ra[i].w);
    }
#pragma unroll
    for (int i = 0; i < BITERS; i++) {
        int idx = tid + i * 256; int r, c;
        if (BLAYOUT == 0) {
            r = (BN == 128) ? (idx >> 5) : (idx >> 4);
            c = (BN == 128) ? ((idx & 31) << 2) : ((idx & 15) << 2);
        } else { r = idx >> 3; c = (idx & 7) << 2; }
        unsigned* p = &Bs[r * BP + c];
        p[0] = f2tf(rb[i].x); p[1] = f2tf(rb[i].y);
        p[2] = f2tf(rb[i].z); p[3] = f2tf(rb[i].w);
    }
    __syncthreads();

    for (int t = 0; t < ktiles; t++) {
        // ---- prefetch next k-tile into regs (overlaps with MMA below) ----
        if (t + 1 < ktiles) {
            int k0 = (t + 1) * BK;
#pragma unroll
            for (int i = 0; i < 4; i++) {
                int idx = tid + i * 256; int r = idx >> 3, c = (idx & 7) << 2;
                int grow = bm + r;
                ra[i] = (grow < M) ? *(const float4*)(A + (size_t)grow * lda + k0 + c)
                                   : make_float4(0.f, 0.f, 0.f, 0.f);
            }
            if (BLAYOUT == 0) {
#pragma unroll
                for (int i = 0; i < BITERS; i++) {
                    int idx = tid + i * 256;
                    int r = (BN == 128) ? (idx >> 5) : (idx >> 4);
                    int c = (BN == 128) ? ((idx & 31) << 2) : ((idx & 15) << 2);
                    rb[i] = *(const float4*)(Bg + (size_t)(k0 + r) * ldb + bn + c);
                }
            } else {
#pragma unroll
                for (int i = 0; i < BITERS; i++) {
                    int idx = tid + i * 256; int r = idx >> 3, c = (idx & 7) << 2;
                    rb[i] = *(const float4*)(Bg + (size_t)(bn + r) * ldb + k0 + c);
                }
            }
        }

        // ---- compute from smem ----
#pragma unroll
        for (int ks = 0; ks < BK / 8; ks++) {
            const int k = ks * 8;
            unsigned af[MT][4], bf[NT][2];
#pragma unroll
            for (int mt = 0; mt < MT; mt++) {
                int mb = wm + mt * 16;
                af[mt][0] = As[(mb + g)     * AP + k + tg];
                af[mt][1] = As[(mb + g + 8) * AP + k + tg];
                af[mt][2] = As[(mb + g)     * AP + k + tg + 4];
                af[mt][3] = As[(mb + g + 8) * AP + k + tg + 4];
            }
#pragma unroll
            for (int nt = 0; nt < NT; nt++) {
                int nb = wn + nt * 8;
                if (BLAYOUT == 0) {
                    bf[nt][0] = Bs[(k + tg)     * BP + nb + g];
                    bf[nt][1] = Bs[(k + tg + 4) * BP + nb + g];
                } else {
                    bf[nt][0] = Bs[(nb + g) * BP + k + tg];
                    bf[nt][1] = Bs[(nb + g) * BP + k + tg + 4];
                }
            }
#pragma unroll
            for (int mt = 0; mt < MT; mt++)
#pragma unroll
                for (int nt = 0; nt < NT; nt++)
                    mma_tf32(acc[mt][nt], af[mt], bf[nt]);
        }
        __syncthreads();

        // ---- write prefetched regs to smem ----
        if (t + 1 < ktiles) {
#pragma unroll
            for (int i = 0; i < 4; i++) {
                int idx = tid + i * 256; int r = idx >> 3, c = (idx & 7) << 2;
                unsigned* p = &As[r * AP + c];
                p[0] = f2tf(ra[i].x); p[1] = f2tf(ra[i].y);
                p[2] = f2tf(ra[i].z); p[3] = f2tf(ra[i].w);
            }
#pragma unroll
            for (int i = 0; i < BITERS; i++) {
                int idx = tid + i * 256; int r, c;
                if (BLAYOUT == 0) {
                    r = (BN == 128) ? (idx >> 5) : (idx >> 4);
                    c = (BN == 128) ? ((idx & 31) << 2) : ((idx & 15) << 2);
                } else { r = idx >> 3; c = (idx & 7) << 2; }
                unsigned* p = &Bs[r * BP + c];
                p[0] = f2tf(rb[i].x); p[1] = f2tf(rb[i].y);
                p[2] = f2tf(rb[i].z); p[3] = f2tf(rb[i].w);
            }
            __syncthreads();
        }
    }

    // ---- epilogue ----
#pragma unroll
    for (int mt = 0; mt < MT; mt++) {
#pragma unroll
        for (int nt = 0; nt < NT; nt++) {
            int row0 = bm + wm + mt * 16 + g;
            int col  = bn + wn + nt * 8 + tg * 2;
            float b0 = bias ? bias[col]     : 0.f;
            float b1 = bias ? bias[col + 1] : 0.f;
            float v0 = acc[mt][nt][0] * scale + b0;
            float v1 = acc[mt][nt][1] * scale + b1;
            float v2 = acc[mt][nt][2] * scale + b0;
            float v3 = acc[mt][nt][3] * scale + b1;
            if (relu) {
                v0 = fmaxf(v0, 0.f); v1 = fmaxf(v1, 0.f);
                v2 = fmaxf(v2, 0.f); v3 = fmaxf(v3, 0.f);
            }
            if (row0 < M)     *(float2*)(C + (size_t)row0 * ldc + col)       = make_float2(v0, v1);
            if (row0 + 8 < M) *(float2*)(C + (size_t)(row0 + 8) * ldc + col) = make_float2(v2, v3);
        }
    }
}

__global__ void __launch_bounds__(256) k_gemm128(
    const float* __restrict__ A, int lda, const float* __restrict__ B, int ldb,
    const float* __restrict__ bias, float* __restrict__ C, int ldc, int M, int Kd, int relu)
{
    mma_gemm_tile<0, 128>(A, lda, B, ldb, bias, C, ldc, M, Kd,
                          blockIdx.x * 128, blockIdx.y * 128, relu, 1.f);
}

__global__ void __launch_bounds__(256) k_moe_gemm_mma(
    const float* __restrict__ Abase, const float* __restrict__ Wbase,
    const float* __restrict__ bbase, float* __restrict__ Cbase, int Kd, int Nn, int relu)
{
    int e = blockIdx.z;
    int cnt = g_cnt[e];
    int bm = blockIdx.x * 128;
    if (bm >= cnt) return;
    int off = g_off[e];
    mma_gemm_tile<0, 128>(Abase + (size_t)off * Kd, Kd,
                          Wbase + (size_t)e * Kd * Nn, Nn,
                          bbase + (size_t)e * Nn,
                          Cbase + (size_t)off * Nn, Nn,
                          cnt, Kd, bm, blockIdx.y * 128, relu, 1.f);
}

__global__ void __launch_bounds__(256) k_scores_mma(
    const float* __restrict__ Q, const float* __restrict__ K, float* __restrict__ SC)
{
    int bh = blockIdx.z;
    int b = bh >> 4, h = bh & 15;
    mma_gemm_tile<1, 128>(Q + (size_t)b * Sseq * Dm + h * DHd, Dm,
                          K + (size_t)b * Sseq * Dm + h * DHd, Dm,
                          nullptr,
                          SC + (size_t)bh * Sseq * Sseq, Sseq,
                          Sseq, DHd, blockIdx.x * 128, blockIdx.y * 128, 0, 0.125f);
}

__global__ void __launch_bounds__(256) k_av_mma(
    const float* __restrict__ SC, const float* __restrict__ V, float* __restrict__ AT)
{
    int bh = blockIdx.y;
    int b = bh >> 4, h = bh & 15;
    mma_gemm_tile<0, 64>(SC + (size_t)bh * Sseq * Sseq, Sseq,
                         V + (size_t)b * Sseq * Dm + h * DHd, Dm,
                         nullptr,
                         AT + (size_t)b * Sseq * Dm + h * DHd, Dm,
                         Sseq, Sseq, blockIdx.x * 128, 0, 0, 1.f);
}

// ---------------- softmax ----------------
__global__ void k_softmax(float* __restrict__ SC)
{
    size_t row = blockIdx.x;
    float* p = SC + row * Sseq;
    int tid = threadIdx.x;
    float v[8];
    float mx = -1e30f;
#pragma unroll
    for (int i = 0; i < 8; i++) { v[i] = p[tid + i * 256]; mx = fmaxf(mx, v[i]); }
    __shared__ float red[256];
    red[tid] = mx; __syncthreads();
    for (int st = 128; st > 0; st >>= 1) {
        if (tid < st) red[tid] = fmaxf(red[tid], red[tid + st]);
        __syncthreads();
    }
    mx = red[0]; __syncthreads();
    float sm = 0.f;
#pragma unroll
    for (int i = 0; i < 8; i++) { v[i] = expf(v[i] - mx); sm += v[i]; }
    red[tid] = sm; __syncthreads();
    for (int st = 128; st > 0; st >>= 1) {
        if (tid < st) red[tid] += red[tid + st];
        __syncthreads();
    }
    float inv = 1.f / red[0];
#pragma unroll
    for (int i = 0; i < 8; i++) p[tid + i * 256] = v[i] * inv;
}

// ---------------- layernorm(residual) ----------------
__global__ void k_ln_res(const float* __restrict__ X, const float* __restrict__ R,
                         const float* __restrict__ gw, const float* __restrict__ bw,
                         float* __restrict__ O)
{
    int t = blockIdx.x, tid = threadIdx.x;
    const float* xp = X + (size_t)t * Dm;
    const float* rp = R + (size_t)t * Dm;
    float v[4]; float s = 0.f;
#pragma unroll
    for (int i = 0; i < 4; i++) { int d = tid + i * 256; v[i] = xp[d] + rp[d]; s += v[i]; }
    __shared__ float red[256];
    red[tid] = s; __syncthreads();
    for (int st = 128; st > 0; st >>= 1) {
        if (tid < st) red[tid] += red[tid + st];
        __syncthreads();
    }
    float mean = red[0] * (1.f / Dm);
    __syncthreads();
    float s2 = 0.f;
#pragma unroll
    for (int i = 0; i < 4; i++) { float dd = v[i] - mean; s2 += dd * dd; }
    red[tid] = s2; __syncthreads();
    for (int st = 128; st > 0; st >>= 1) {
        if (tid < st) red[tid] += red[tid + st];
        __syncthreads();
    }
    float rstd = rsqrtf(red[0] * (1.f / Dm) + 1e-5f);
    float* op = O + (size_t)t * Dm;
#pragma unroll
    for (int i = 0; i < 4; i++) {
        int d = tid + i * 256;
        op[d] = (v[i] - mean) * rstd * gw[d] + bw[d];
    }
}

// ---------------- MoE routing / dispatch ----------------
__global__ void k_moe_init()
{
    int tid = threadIdx.x;
    if (tid < Ee) { g_cnt[tid] = 0; g_cur[tid] = 0; }
    for (int i = tid; i < NKCAP; i += 256) g_row_tok[i] = -1;
}

__global__ void k_router(const float* __restrict__ X,
                         const float* __restrict__ rw,
                         const float* __restrict__ rb,
                         int mode)
{
    int t = blockIdx.x, tid = threadIdx.x;
    const float* xp = X + (size_t)t * Dm;
    float loc[Ee];
#pragma unroll
    for (int e = 0; e < Ee; e++) loc[e] = 0.f;
    for (int d = tid; d < Dm; d += 256) {
        float xv = xp[d];
#pragma unroll
        for (int e = 0; e < Ee; e++) loc[e] += xv * rw[d * Ee + e];
    }
    __shared__ float red[256 * Ee];
#pragma unroll
    for (int e = 0; e < Ee; e++) red[tid * Ee + e] = loc[e];
    __syncthreads();
    for (int st = 128; st > 0; st >>= 1) {
        if (tid < st)
#pragma unroll
            for (int e = 0; e < Ee; e++)
                red[tid * Ee + e] += red[(tid + st) * Ee + e];
        __syncthreads();
    }
    if (tid == 0) {
        float lg[Ee], mx = -1e30f;
#pragma unroll
        for (int e = 0; e < Ee; e++) { lg[e] = red[e] + rb[e]; mx = fmaxf(mx, lg[e]); }
        float sm = 0.f;
#pragma unroll
        for (int e = 0; e < Ee; e++) { lg[e] = expf(lg[e] - mx); sm += lg[e]; }
        float inv = 1.f / sm;
#pragma unroll
        for (int e = 0; e < Ee; e++) lg[e] *= inv;
        int e0 = 0;
#pragma unroll
        for (int e = 1; e < Ee; e++) if (lg[e] > lg[e0]) e0 = e;
        int e1 = -1;
#pragma unroll
        for (int e = 0; e < Ee; e++)
            if (e != e0 && (e1 < 0 || lg[e] > lg[e1])) e1 = e;
        if (mode == 0) {
            float g0 = lg[e0], g1 = lg[e1], gs = g0 + g1;
            g_tok_e[t * 2] = e0;  g_tok_e[t * 2 + 1] = e1;
            g_tok_g[t * 2] = g0 / gs; g_tok_g[t * 2 + 1] = g1 / gs;
            atomicAdd(&g_cnt[e0], 1); atomicAdd(&g_cnt[e1], 1);
        } else {
#pragma unroll
            for (int e = 0; e < Ee; e++) g_auxp[t * Ee + e] = lg[e];
            g_auxi[t * 2] = e0; g_auxi[t * 2 + 1] = e1;
        }
    }
}

__global__ void k_offsets()
{
    if (threadIdx.x == 0) {
        int acc = 0;
        for (int e = 0; e < Ee; e++) {
            g_off[e] = acc;
            acc += ((g_cnt[e] + 127) >> 7) << 7;
        }
        g_off[Ee] = acc;
    }
}

__global__ void k_gather(const float* __restrict__ X)
{
    int t = blockIdx.x, tid = threadIdx.x;
    __shared__ int spos[TOPK];
    if (tid == 0) {
#pragma unroll
        for (int k = 0; k < TOPK; k++) {
            int e = g_tok_e[t * 2 + k];
            int p = g_off[e] + atomicAdd(&g_cur[e], 1);
            spos[k] = p;
            g_row_tok[p] = t;
            g_row_gate[p] = g_tok_g[t * 2 + k];
        }
    }
    __syncthreads();
    const float4* src = reinterpret_cast<const float4*>(X + (size_t)t * Dm);
#pragma unroll
    for (int k = 0; k < TOPK; k++) {
        float4* dst = reinterpret_cast<float4*>(g_XG + (size_t)spos[k] * Dm);
        dst[tid] = src[tid];
    }
}

__global__ void k_zero_mo()
{
    int t = blockIdx.x, tid = threadIdx.x;
    float4 z = make_float4(0.f, 0.f, 0.f, 0.f);
    reinterpret_cast<float4*>(g_MO + (size_t)t * Dm)[tid] = z;
}

__global__ void k_scatter()
{
    int p = blockIdx.x;
    int t = g_row_tok[p];
    if (t < 0) return;
    float gt = g_row_gate[p];
    int tid = threadIdx.x;
    for (int d = tid; d < Dm; d += 256)
        atomicAdd(&g_MO[(size_t)t * Dm + d], gt * g_YG[(size_t)p * Dm + d]);
}

__global__ void k_aux_final(float* __restrict__ out)
{
    int tid = threadIdx.x;
    float imp[Ee];
#pragma unroll
    for (int e = 0; e < Ee; e++) imp[e] = 0.f;
    for (int t = tid; t < Ntok; t += 256)
#pragma unroll
        for (int e = 0; e < Ee; e++) imp[e] += g_auxp[t * Ee + e];
    float ld[Ee];
#pragma unroll
    for (int e = 0; e < Ee; e++) ld[e] = 0.f;
    for (int i = tid; i < Ntok * TOPK; i += 256) ld[g_auxi[i]] += 1.f;

    __shared__ float red[256 * Ee];
    __shared__ float simp[Ee];
#pragma unroll
    for (int e = 0; e < Ee; e++) red[tid * Ee + e] = imp[e];
    __syncthreads();
    for (int st = 128; st > 0; st >>= 1) {
        if (tid < st)
#pragma unroll
            for (int e = 0; e < Ee; e++)
                red[tid * Ee + e] += red[(tid + st) * Ee + e];
        __syncthreads();
    }
    if (tid == 0)
#pragma unroll
        for (int e = 0; e < Ee; e++) simp[e] = red[e];
    __syncthreads();
#pragma unroll
    for (int e = 0; e < Ee; e++) red[tid * Ee + e] = ld[e];
    __syncthreads();
    for (int st = 128; st > 0; st >>= 1) {
        if (tid < st)
#pragma unroll
            for (int e = 0; e < Ee; e++)
                red[tid * Ee + e] += red[(tid + st) * Ee + e];
        __syncthreads();
    }
    if (tid == 0) {
        float aux = 0.f;
#pragma unroll
        for (int e = 0; e < Ee; e++)
            aux += (simp[e] / (float)Ntok) * (red[e] / (float)(Ntok * TOPK));
        out[0] = (float)Ee * aux;
    }
}

// ---------------- host orchestration ----------------
extern "C" void kernel_launch(void* const* d_in, const int* in_sizes, int n_in,
                              void* d_out, int out_size)
{
    (void)in_sizes; (void)n_in;
    const float* x     = (const float*)d_in[0];
    const float* enc   = (const float*)d_in[1];
    const float* sa_wq = (const float*)d_in[2];
    const float* sa_bq = (const float*)d_in[3];
    const float* sa_wk = (const float*)d_in[4];
    const float* sa_bk = (const float*)d_in[5];
    const float* sa_wv = (const float*)d_in[6];
    const float* sa_bv = (const float*)d_in[7];
    const float* sa_wo = (const float*)d_in[8];
    const float* sa_bo = (const float*)d_in[9];
    const float* ca_wq = (const float*)d_in[10];
    const float* ca_bq = (const float*)d_in[11];
    const float* ca_wk = (const float*)d_in[12];
    const float* ca_bk = (const float*)d_in[13];
    const float* ca_wv = (const float*)d_in[14];
    const float* ca_bv = (const float*)d_in[15];
    const float* ca_wo = (const float*)d_in[16];
    const float* ca_bo = (const float*)d_in[17];
    const float* n1_g  = (const float*)d_in[18];
    const float* n1_b  = (const float*)d_in[19];
    const float* n2_g  = (const float*)d_in[20];
    const float* n2_b  = (const float*)d_in[21];
    const float* n3_g  = (const float*)d_in[22];
    const float* n3_b  = (const float*)d_in[23];
    const float* r_w   = (const float*)d_in[24];
    const float* r_b   = (const float*)d_in[25];
    const float* e_w1  = (const float*)d_in[26];
    const float* e_b1  = (const float*)d_in[27];
    const float* e_w2  = (const float*)d_in[28];
    const float* e_b2  = (const float*)d_in[29];

    void *pQ, *pK, *pV, *pAT, *pPR, *pX1, *pX2, *pSC, *pXG, *pHB, *pYG, *pMO;
    cudaGetSymbolAddress(&pQ,  g_Q);
    cudaGetSymbolAddress(&pK,  g_K);
    cudaGetSymbolAddress(&pV,  g_V);
    cudaGetSymbolAddress(&pAT, g_AT);
    cudaGetSymbolAddress(&pPR, g_PR);
    cudaGetSymbolAddress(&pX1, g_X1);
    cudaGetSymbolAddress(&pX2, g_X2);
    cudaGetSymbolAddress(&pSC, g_SC);
    cudaGetSymbolAddress(&pXG, g_XG);
    cudaGetSymbolAddress(&pHB, g_HB);
    cudaGetSymbolAddress(&pYG, g_YG);
    cudaGetSymbolAddress(&pMO, g_MO);
    float* Q  = (float*)pQ;  float* K  = (float*)pK;  float* V  = (float*)pV;
    float* AT = (float*)pAT; float* PR = (float*)pPR;
    float* X1 = (float*)pX1; float* X2 = (float*)pX2;
    float* SC = (float*)pSC;
    float* XG = (float*)pXG; float* HB = (float*)pHB; float* YG = (float*)pYG;
    float* out = (float*)d_out;

    dim3 blk(256);
    dim3 gProj(Ntok / 128, Dm / 128);
    dim3 gScore(Sseq / 128, Sseq / 128, Bbat * Hh);
    dim3 gAV(Sseq / 128, Bbat * Hh);

    // ---- self attention ----
    k_gemm128<<<gProj, blk>>>(x, Dm, sa_wq, Dm, sa_bq, Q, Dm, Ntok, Dm, 0);
    k_gemm128<<<gProj, blk>>>(x, Dm, sa_wk, Dm, sa_bk, K, Dm, Ntok, Dm, 0);
    k_gemm128<<<gProj, blk>>>(x, Dm, sa_wv, Dm, sa_bv, V, Dm, Ntok, Dm, 0);
    k_scores_mma<<<gScore, blk>>>(Q, K, SC);
    k_softmax<<<Bbat * Hh * Sseq, blk>>>(SC);
    k_av_mma<<<gAV, blk>>>(SC, V, AT);
    k_gemm128<<<gProj, blk>>>(AT, Dm, sa_wo, Dm, sa_bo, PR, Dm, Ntok, Dm, 0);
    k_ln_res<<<Ntok, blk>>>(x, PR, n1_g, n1_b, X1);

    // ---- cross attention ----
    k_gemm128<<<gProj, blk>>>(X1,  Dm, ca_wq, Dm, ca_bq, Q, Dm, Ntok, Dm, 0);
    k_gemm128<<<gProj, blk>>>(enc, Dm, ca_wk, Dm, ca_bk, K, Dm, Ntok, Dm, 0);
    k_gemm128<<<gProj, blk>>>(enc, Dm, ca_wv, Dm, ca_bv, V, Dm, Ntok, Dm, 0);
    k_scores_mma<<<gScore, blk>>>(Q, K, SC);
    k_softmax<<<Bbat * Hh * Sseq, blk>>>(SC);
    k_av_mma<<<gAV, blk>>>(SC, V, AT);
    k_gemm128<<<gProj, blk>>>(AT, Dm, ca_wo, Dm, ca_bo, PR, Dm, Ntok, Dm, 0);
    k_ln_res<<<Ntok, blk>>>(X1, PR, n2_g, n2_b, X2);

    // ---- MoE (sparse top-2 dispatch) ----
    k_moe_init<<<1, blk>>>();
    k_router<<<Ntok, blk>>>(X2, r_w, r_b, 0);
    k_offsets<<<1, 1>>>();
    k_gather<<<Ntok, blk>>>(X2);
    k_moe_gemm_mma<<<dim3(Ntok / 128, Ff / 128, Ee), blk>>>(XG, e_w1, e_b1, HB, Dm, Ff, 1);
    k_moe_gemm_mma<<<dim3(Ntok / 128, Dm / 128, Ee), blk>>>(HB, e_w2, e_b2, YG, Ff, Dm, 0);
    k_zero_mo<<<Ntok, blk>>>();
    k_scatter<<<NKCAP, blk>>>();
    k_ln_res<<<Ntok, blk>>>(X2, (float*)pMO, n3_g, n3_b, out);

    // ---- aux loss (router recompute on OUTPUT, per reference) ----
    if (out_size > Ntok * Dm) {
        k_router<<<Ntok, blk>>>(out, r_w, r_b, 1);
        k_aux_final<<<1, blk>>>(out + (out_size - 1));
    }
}

// round 3
// speedup vs baseline: 3.3044x; 1.2577x over previous
#include <cuda_runtime.h>
#include <math.h>

// ---------------- problem constants ----------------
#define Dm      1024
#define Hh      16
#define DHd     64
#define Ff      4096
#define Ee      8
#define TOPK    2
#define Bbat    2
#define Sseq    2048
#define Ntok    4096
#define NKCAP   16384

// flash attention tiling
#define QT      128
#define KC      64
#define KSP     68
#define VSP     72
#define PSP     68
#define FLASH_SMEM ((KC*KSP + KC*VSP + QT*PSP) * 4)

// ---------------- device scratch ----------------
__device__ float g_Q [Ntok * Dm];
__device__ float g_K [Ntok * Dm];
__device__ float g_V [Ntok * Dm];
__device__ float g_AT[Ntok * Dm];
__device__ float g_PR[Ntok * Dm];
__device__ float g_X1[Ntok * Dm];
__device__ float g_X2[Ntok * Dm];

__device__ float g_XG[(size_t)NKCAP * Dm];
__device__ float g_HB[(size_t)NKCAP * Ff];
__device__ float g_YG[(size_t)NKCAP * Dm];
__device__ float g_MO[Ntok * Dm];

__device__ int   g_tok_e[Ntok * TOPK];
__device__ float g_tok_g[Ntok * TOPK];
__device__ int   g_cnt[Ee];
__device__ int   g_cur[Ee];
__device__ int   g_off[Ee + 1];
__device__ int   g_row_tok[NKCAP];
__device__ float g_row_gate[NKCAP];
__device__ float g_auxp[Ntok * Ee];
__device__ int   g_auxi[Ntok * TOPK];

// ---------------- tf32 helpers ----------------
__device__ __forceinline__ unsigned f2tf(float f) {
    unsigned r;
    asm("cvt.rna.tf32.f32 %0, %1;" : "=r"(r) : "f"(f));
    return r;
}

__device__ __forceinline__ void mma_tf32(float* c, const unsigned* a, const unsigned* b) {
    asm volatile(
        "mma.sync.aligned.m16n8k8.row.col.f32.tf32.tf32.f32 "
        "{%0,%1,%2,%3},{%4,%5,%6,%7},{%8,%9},{%0,%1,%2,%3};\n"
        : "+f"(c[0]), "+f"(c[1]), "+f"(c[2]), "+f"(c[3])
        : "r"(a[0]), "r"(a[1]), "r"(a[2]), "r"(a[3]), "r"(b[0]), "r"(b[1]));
}

// ---------------- flash attention (fused QK^T -> softmax -> PV) ----------------
// grid: (Sseq/QT, Bbat*Hh), block 256 (8 warps, 16 q-rows each)
__global__ void __launch_bounds__(256) k_flash(
    const float* __restrict__ Qg, const float* __restrict__ Kg,
    const float* __restrict__ Vg, float* __restrict__ AT)
{
    extern __shared__ float sm[];
    unsigned* Ks = (unsigned*)sm;                 // [KC][KSP] tf32, layout [n][k]
    unsigned* Vs = Ks + KC * KSP;                 // [KC][VSP] tf32, layout [k][n]
    unsigned* Ps = Vs + KC * VSP;                 // [QT][PSP] tf32

    const int bh = blockIdx.y;
    const int b = bh >> 4, h = bh & 15;
    const int q0 = blockIdx.x * QT;
    const int tid = threadIdx.x;
    const int lane = tid & 31;
    const int wid = tid >> 5;
    const int g = lane >> 2;
    const int tg = lane & 3;
    const int wrow = wid * 16;

    const float* Qp = Qg + (size_t)b * Sseq * Dm + h * DHd;
    const float* Kp = Kg + (size_t)b * Sseq * Dm + h * DHd;
    const float* Vp = Vg + (size_t)b * Sseq * Dm + h * DHd;

    // Q fragments in registers: 8 k-steps x 4 regs
    unsigned qf[8][4];
#pragma unroll
    for (int kt = 0; kt < 8; kt++) {
        int k = kt * 8;
        qf[kt][0] = f2tf(Qp[(size_t)(q0 + wrow + g)     * Dm + k + tg]);
        qf[kt][1] = f2tf(Qp[(size_t)(q0 + wrow + g + 8) * Dm + k + tg]);
        qf[kt][2] = f2tf(Qp[(size_t)(q0 + wrow + g)     * Dm + k + tg + 4]);
        qf[kt][3] = f2tf(Qp[(size_t)(q0 + wrow + g + 8) * Dm + k + tg + 4]);
    }

    float oacc[8][4];
#pragma unroll
    for (int i = 0; i < 8; i++)
#pragma unroll
        for (int j = 0; j < 4; j++) oacc[i][j] = 0.f;
    float m0 = -1e30f, m1 = -1e30f, l0 = 0.f, l1 = 0.f;

    for (int c = 0; c < Sseq / KC; c++) {
        int kc0 = c * KC;
        // ---- load K,V chunk (KC x 64) ----
#pragma unroll
        for (int i = 0; i < 4; i++) {
            int idx = tid + i * 256;
            int r = idx >> 4, cc = (idx & 15) << 2;
            float4 kv = *(const float4*)(Kp + (size_t)(kc0 + r) * Dm + cc);
            unsigned* p = &Ks[r * KSP + cc];
            p[0] = f2tf(kv.x); p[1] = f2tf(kv.y); p[2] = f2tf(kv.z); p[3] = f2tf(kv.w);
            float4 vv = *(const float4*)(Vp + (size_t)(kc0 + r) * Dm + cc);
            unsigned* q = &Vs[r * VSP + cc];
            q[0] = f2tf(vv.x); q[1] = f2tf(vv.y); q[2] = f2tf(vv.z); q[3] = f2tf(vv.w);
        }
        __syncthreads();

        // ---- S = Q K^T (16 x 64 per warp) ----
        float sacc[8][4];
#pragma unroll
        for (int i = 0; i < 8; i++)
#pragma unroll
            for (int j = 0; j < 4; j++) sacc[i][j] = 0.f;
#pragma unroll
        for (int kt = 0; kt < 8; kt++) {
            int k = kt * 8;
            unsigned bf[8][2];
#pragma unroll
            for (int nt = 0; nt < 8; nt++) {
                bf[nt][0] = Ks[(nt * 8 + g) * KSP + k + tg];
                bf[nt][1] = Ks[(nt * 8 + g) * KSP + k + tg + 4];
            }
#pragma unroll
            for (int nt = 0; nt < 8; nt++)
                mma_tf32(sacc[nt], qf[kt], bf[nt]);
        }

        // ---- online softmax ----
        float mx0 = -1e30f, mx1 = -1e30f;
#pragma unroll
        for (int nt = 0; nt < 8; nt++) {
            sacc[nt][0] *= 0.125f; sacc[nt][1] *= 0.125f;
            sacc[nt][2] *= 0.125f; sacc[nt][3] *= 0.125f;
            mx0 = fmaxf(mx0, fmaxf(sacc[nt][0], sacc[nt][1]));
            mx1 = fmaxf(mx1, fmaxf(sacc[nt][2], sacc[nt][3]));
        }
        mx0 = fmaxf(mx0, __shfl_xor_sync(0xffffffff, mx0, 1));
        mx0 = fmaxf(mx0, __shfl_xor_sync(0xffffffff, mx0, 2));
        mx1 = fmaxf(mx1, __shfl_xor_sync(0xffffffff, mx1, 1));
        mx1 = fmaxf(mx1, __shfl_xor_sync(0xffffffff, mx1, 2));
        float nm0 = fmaxf(m0, mx0), nm1 = fmaxf(m1, mx1);
        float sc0 = __expf(m0 - nm0), sc1 = __expf(m1 - nm1);
        float ps0 = 0.f, ps1 = 0.f;
#pragma unroll
        for (int nt = 0; nt < 8; nt++) {
            float p00 = __expf(sacc[nt][0] - nm0);
            float p01 = __expf(sacc[nt][1] - nm0);
            float p10 = __expf(sacc[nt][2] - nm1);
            float p11 = __expf(sacc[nt][3] - nm1);
            ps0 += p00 + p01; ps1 += p10 + p11;
            int col = nt * 8 + tg * 2;
            *(uint2*)&Ps[(wrow + g)     * PSP + col] = make_uint2(f2tf(p00), f2tf(p01));
            *(uint2*)&Ps[(wrow + g + 8) * PSP + col] = make_uint2(f2tf(p10), f2tf(p11));
        }
        ps0 += __shfl_xor_sync(0xffffffff, ps0, 1);
        ps0 += __shfl_xor_sync(0xffffffff, ps0, 2);
        ps1 += __shfl_xor_sync(0xffffffff, ps1, 1);
        ps1 += __shfl_xor_sync(0xffffffff, ps1, 2);
        l0 = l0 * sc0 + ps0; l1 = l1 * sc1 + ps1;
        m0 = nm0; m1 = nm1;
#pragma unroll
        for (int nt = 0; nt < 8; nt++) {
            oacc[nt][0] *= sc0; oacc[nt][1] *= sc0;
            oacc[nt][2] *= sc1; oacc[nt][3] *= sc1;
        }
        __syncwarp();

        // ---- O += P V ----
#pragma unroll
        for (int kt = 0; kt < 8; kt++) {
            int k = kt * 8;
            unsigned af[4];
            af[0] = Ps[(wrow + g)     * PSP + k + tg];
            af[1] = Ps[(wrow + g + 8) * PSP + k + tg];
            af[2] = Ps[(wrow + g)     * PSP + k + tg + 4];
            af[3] = Ps[(wrow + g + 8) * PSP + k + tg + 4];
            unsigned bf[8][2];
#pragma unroll
            for (int nt = 0; nt < 8; nt++) {
                bf[nt][0] = Vs[(k + tg)     * VSP + nt * 8 + g];
                bf[nt][1] = Vs[(k + tg + 4) * VSP + nt * 8 + g];
            }
#pragma unroll
            for (int nt = 0; nt < 8; nt++)
                mma_tf32(oacc[nt], af, bf[nt]);
        }
        __syncthreads();
    }

    // ---- epilogue ----
    float inv0 = 1.f / l0, inv1 = 1.f / l1;
    float* Op = AT + (size_t)b * Sseq * Dm + h * DHd;
#pragma unroll
    for (int nt = 0; nt < 8; nt++) {
        int col = nt * 8 + tg * 2;
        *(float2*)(Op + (size_t)(q0 + wrow + g) * Dm + col) =
            make_float2(oacc[nt][0] * inv0, oacc[nt][1] * inv0);
        *(float2*)(Op + (size_t)(q0 + wrow + g + 8) * Dm + col) =
            make_float2(oacc[nt][2] * inv1, oacc[nt][3] * inv1);
    }
}

// ---------------- generic tensor-core GEMM tile ----------------
template<int BLAYOUT, int BN>
__device__ __forceinline__ void mma_gemm_tile(
    const float* __restrict__ A, int lda,
    const float* __restrict__ Bg, int ldb,
    const float* __restrict__ bias,
    float* __restrict__ C, int ldc,
    int M, int Kd, int bm, int bn, int relu, float scale)
{
    constexpr int BM = 128, BK = 32;
    constexpr int WC = (BN == 128) ? 4 : 2;
    constexpr int WM = (BN == 128) ? 64 : 32;
    constexpr int WN = 32;
    constexpr int MT = WM / 16;
    constexpr int NT = WN / 8;
    constexpr int AP = BK + 4;
    constexpr int BP = (BLAYOUT == 0) ? (BN + 8) : (BK + 4);
    constexpr int BROWS = (BLAYOUT == 0) ? BK : BN;
    constexpr int BITERS = (BK * BN) / 1024;

    __shared__ unsigned As[BM * AP];
    __shared__ unsigned Bs[BROWS * BP];

    const int tid  = threadIdx.x;
    const int lane = tid & 31;
    const int wid  = tid >> 5;
    const int wm = (wid / WC) * WM;
    const int wn = (wid % WC) * WN;
    const int g  = lane >> 2;
    const int tg = lane & 3;

    float acc[MT][NT][4];
#pragma unroll
    for (int i = 0; i < MT; i++)
#pragma unroll
        for (int j = 0; j < NT; j++)
#pragma unroll
            for (int q = 0; q < 4; q++) acc[i][j][q] = 0.f;

    float4 ra[4], rb[BITERS];
    const int ktiles = Kd / BK;

#pragma unroll
    for (int i = 0; i < 4; i++) {
        int idx = tid + i * 256; int r = idx >> 3, c = (idx & 7) << 2;
        int grow = bm + r;
        ra[i] = (grow < M) ? *(const float4*)(A + (size_t)grow * lda + c)
                           : make_float4(0.f, 0.f, 0.f, 0.f);
    }
    if (BLAYOUT == 0) {
#pragma unroll
        for (int i = 0; i < BITERS; i++) {
            int idx = tid + i * 256;
            int r = (BN == 128) ? (idx >> 5) : (idx >> 4);
            int c = (BN == 128) ? ((idx & 31) << 2) : ((idx & 15) << 2);
            rb[i] = *(const float4*)(Bg + (size_t)r * ldb + bn + c);
        }
    } else {
#pragma unroll
        for (int i = 0; i < BITERS; i++) {
            int idx = tid + i * 256; int r = idx >> 3, c = (idx & 7) << 2;
            rb[i] = *(const float4*)(Bg + (size_t)(bn + r) * ldb + c);
        }
    }
#pragma unroll
    for (int i = 0; i < 4; i++) {
        int idx = tid + i * 256; int r = idx >> 3, c = (idx & 7) << 2;
        unsigned* p = &As[r * AP + c];
        p[0] = f2tf(ra[i].x); p[1] = f2tf(ra[i].y);
        p[2] = f2tf(ra[i].z); p[3] = f2tf(ra[i].w);
    }
#pragma unroll
    for (int i = 0; i < BITERS; i++) {
        int idx = tid + i * 256; int r, c;
        if (BLAYOUT == 0) {
            r = (BN == 128) ? (idx >> 5) : (idx >> 4);
            c = (BN == 128) ? ((idx & 31) << 2) : ((idx & 15) << 2);
        } else { r = idx >> 3; c = (idx & 7) << 2; }
        unsigned* p = &Bs[r * BP + c];
        p[0] = f2tf(rb[i].x); p[1] = f2tf(rb[i].y);
        p[2] = f2tf(rb[i].z); p[3] = f2tf(rb[i].w);
    }
    __syncthreads();

    for (int t = 0; t < ktiles; t++) {
        if (t + 1 < ktiles) {
            int k0 = (t + 1) * BK;
#pragma unroll
            for (int i = 0; i < 4; i++) {
                int idx = tid + i * 256; int r = idx >> 3, c = (idx & 7) << 2;
                int grow = bm + r;
                ra[i] = (grow < M) ? *(const float4*)(A + (size_t)grow * lda + k0 + c)
                                   : make_float4(0.f, 0.f, 0.f, 0.f);
            }
            if (BLAYOUT == 0) {
#pragma unroll
                for (int i = 0; i < BITERS; i++) {
                    int idx = tid + i * 256;
                    int r = (BN == 128) ? (idx >> 5) : (idx >> 4);
                    int c = (BN == 128) ? ((idx & 31) << 2) : ((idx & 15) << 2);
                    rb[i] = *(const float4*)(Bg + (size_t)(k0 + r) * ldb + bn + c);
                }
            } else {
#pragma unroll
                for (int i = 0; i < BITERS; i++) {
                    int idx = tid + i * 256; int r = idx >> 3, c = (idx & 7) << 2;
                    rb[i] = *(const float4*)(Bg + (size_t)(bn + r) * ldb + k0 + c);
                }
            }
        }

#pragma unroll
        for (int ks = 0; ks < BK / 8; ks++) {
            const int k = ks * 8;
            unsigned af[MT][4], bf[NT][2];
#pragma unroll
            for (int mt = 0; mt < MT; mt++) {
                int mb = wm + mt * 16;
                af[mt][0] = As[(mb + g)     * AP + k + tg];
                af[mt][1] = As[(mb + g + 8) * AP + k + tg];
                af[mt][2] = As[(mb + g)     * AP + k + tg + 4];
                af[mt][3] = As[(mb + g + 8) * AP + k + tg + 4];
            }
#pragma unroll
            for (int nt = 0; nt < NT; nt++) {
                int nb = wn + nt * 8;
                if (BLAYOUT == 0) {
                    bf[nt][0] = Bs[(k + tg)     * BP + nb + g];
                    bf[nt][1] = Bs[(k + tg + 4) * BP + nb + g];
                } else {
                    bf[nt][0] = Bs[(nb + g) * BP + k + tg];
                    bf[nt][1] = Bs[(nb + g) * BP + k + tg + 4];
                }
            }
#pragma unroll
            for (int mt = 0; mt < MT; mt++)
#pragma unroll
                for (int nt = 0; nt < NT; nt++)
                    mma_tf32(acc[mt][nt], af[mt], bf[nt]);
        }
        __syncthreads();

        if (t + 1 < ktiles) {
#pragma unroll
            for (int i = 0; i < 4; i++) {
                int idx = tid + i * 256; int r = idx >> 3, c = (idx & 7) << 2;
                unsigned* p = &As[r * AP + c];
                p[0] = f2tf(ra[i].x); p[1] = f2tf(ra[i].y);
                p[2] = f2tf(ra[i].z); p[3] = f2tf(ra[i].w);
            }
#pragma unroll
            for (int i = 0; i < BITERS; i++) {
                int idx = tid + i * 256; int r, c;
                if (BLAYOUT == 0) {
                    r = (BN == 128) ? (idx >> 5) : (idx >> 4);
                    c = (BN == 128) ? ((idx & 31) << 2) : ((idx & 15) << 2);
                } else { r = idx >> 3; c = (idx & 7) << 2; }
                unsigned* p = &Bs[r * BP + c];
                p[0] = f2tf(rb[i].x); p[1] = f2tf(rb[i].y);
                p[2] = f2tf(rb[i].z); p[3] = f2tf(rb[i].w);
            }
            __syncthreads();
        }
    }

#pragma unroll
    for (int mt = 0; mt < MT; mt++) {
#pragma unroll
        for (int nt = 0; nt < NT; nt++) {
            int row0 = bm + wm + mt * 16 + g;
            int col  = bn + wn + nt * 8 + tg * 2;
            float b0 = bias ? bias[col]     : 0.f;
            float b1 = bias ? bias[col + 1] : 0.f;
            float v0 = acc[mt][nt][0] * scale + b0;
            float v1 = acc[mt][nt][1] * scale + b1;
            float v2 = acc[mt][nt][2] * scale + b0;
            float v3 = acc[mt][nt][3] * scale + b1;
            if (relu) {
                v0 = fmaxf(v0, 0.f); v1 = fmaxf(v1, 0.f);
                v2 = fmaxf(v2, 0.f); v3 = fmaxf(v3, 0.f);
            }
            if (row0 < M)     *(float2*)(C + (size_t)row0 * ldc + col)       = make_float2(v0, v1);
            if (row0 + 8 < M) *(float2*)(C + (size_t)(row0 + 8) * ldc + col) = make_float2(v2, v3);
        }
    }
}

__global__ void __launch_bounds__(256) k_gemm128(
    const float* __restrict__ A, int lda, const float* __restrict__ B, int ldb,
    const float* __restrict__ bias, float* __restrict__ C, int ldc, int M, int Kd, int relu)
{
    mma_gemm_tile<0, 128>(A, lda, B, ldb, bias, C, ldc, M, Kd,
                          blockIdx.x * 128, blockIdx.y * 128, relu, 1.f);
}

__global__ void __launch_bounds__(256) k_moe_gemm_mma(
    const float* __restrict__ Abase, const float* __restrict__ Wbase,
    const float* __restrict__ bbase, float* __restrict__ Cbase, int Kd, int Nn, int relu)
{
    int e = blockIdx.z;
    int cnt = g_cnt[e];
    int bm = blockIdx.x * 128;
    if (bm >= cnt) return;
    int off = g_off[e];
    mma_gemm_tile<0, 128>(Abase + (size_t)off * Kd, Kd,
                          Wbase + (size_t)e * Kd * Nn, Nn,
                          bbase + (size_t)e * Nn,
                          Cbase + (size_t)off * Nn, Nn,
                          cnt, Kd, bm, blockIdx.y * 128, relu, 1.f);
}

// ---------------- layernorm(residual) ----------------
__global__ void k_ln_res(const float* __restrict__ X, const float* __restrict__ R,
                         const float* __restrict__ gw, const float* __restrict__ bw,
                         float* __restrict__ O)
{
    int t = blockIdx.x, tid = threadIdx.x;
    const float* xp = X + (size_t)t * Dm;
    const float* rp = R + (size_t)t * Dm;
    float v[4]; float s = 0.f;
#pragma unroll
    for (int i = 0; i < 4; i++) { int d = tid + i * 256; v[i] = xp[d] + rp[d]; s += v[i]; }
    __shared__ float red[256];
    red[tid] = s; __syncthreads();
    for (int st = 128; st > 0; st >>= 1) {
        if (tid < st) red[tid] += red[tid + st];
        __syncthreads();
    }
    float mean = red[0] * (1.f / Dm);
    __syncthreads();
    float s2 = 0.f;
#pragma unroll
    for (int i = 0; i < 4; i++) { float dd = v[i] - mean; s2 += dd * dd; }
    red[tid] = s2; __syncthreads();
    for (int st = 128; st > 0; st >>= 1) {
        if (tid < st) red[tid] += red[tid + st];
        __syncthreads();
    }
    float rstd = rsqrtf(red[0] * (1.f / Dm) + 1e-5f);
    float* op = O + (size_t)t * Dm;
#pragma unroll
    for (int i = 0; i < 4; i++) {
        int d = tid + i * 256;
        op[d] = (v[i] - mean) * rstd * gw[d] + bw[d];
    }
}

// ---------------- MoE routing / dispatch ----------------
__global__ void k_moe_init()
{
    int tid = threadIdx.x;
    if (tid < Ee) { g_cnt[tid] = 0; g_cur[tid] = 0; }
    for (int i = tid; i < NKCAP; i += 256) g_row_tok[i] = -1;
}

__global__ void k_router(const float* __restrict__ X,
                         const float* __restrict__ rw,
                         const float* __restrict__ rb,
                         int mode)
{
    int t = blockIdx.x, tid = threadIdx.x;
    const float* xp = X + (size_t)t * Dm;
    float loc[Ee];
#pragma unroll
    for (int e = 0; e < Ee; e++) loc[e] = 0.f;
    for (int d = tid; d < Dm; d += 256) {
        float xv = xp[d];
#pragma unroll
        for (int e = 0; e < Ee; e++) loc[e] += xv * rw[d * Ee + e];
    }
    __shared__ float red[256 * Ee];
#pragma unroll
    for (int e = 0; e < Ee; e++) red[tid * Ee + e] = loc[e];
    __syncthreads();
    for (int st = 128; st > 0; st >>= 1) {
        if (tid < st)
#pragma unroll
            for (int e = 0; e < Ee; e++)
                red[tid * Ee + e] += red[(tid + st) * Ee + e];
        __syncthreads();
    }
    if (tid == 0) {
        float lg[Ee], mx = -1e30f;
#pragma unroll
        for (int e = 0; e < Ee; e++) { lg[e] = red[e] + rb[e]; mx = fmaxf(mx, lg[e]); }
        float sm = 0.f;
#pragma unroll
        for (int e = 0; e < Ee; e++) { lg[e] = expf(lg[e] - mx); sm += lg[e]; }
        float inv = 1.f / sm;
#pragma unroll
        for (int e = 0; e < Ee; e++) lg[e] *= inv;
        int e0 = 0;
#pragma unroll
        for (int e = 1; e < Ee; e++) if (lg[e] > lg[e0]) e0 = e;
        int e1 = -1;
#pragma unroll
        for (int e = 0; e < Ee; e++)
            if (e != e0 && (e1 < 0 || lg[e] > lg[e1])) e1 = e;
        if (mode == 0) {
            float g0 = lg[e0], g1 = lg[e1], gs = g0 + g1;
            g_tok_e[t * 2] = e0;  g_tok_e[t * 2 + 1] = e1;
            g_tok_g[t * 2] = g0 / gs; g_tok_g[t * 2 + 1] = g1 / gs;
            atomicAdd(&g_cnt[e0], 1); atomicAdd(&g_cnt[e1], 1);
        } else {
#pragma unroll
            for (int e = 0; e < Ee; e++) g_auxp[t * Ee + e] = lg[e];
            g_auxi[t * 2] = e0; g_auxi[t * 2 + 1] = e1;
        }
    }
}

__global__ void k_offsets()
{
    if (threadIdx.x == 0) {
        int acc = 0;
        for (int e = 0; e < Ee; e++) {
            g_off[e] = acc;
            acc += ((g_cnt[e] + 127) >> 7) << 7;
        }
        g_off[Ee] = acc;
    }
}

__global__ void k_gather(const float* __restrict__ X)
{
    int t = blockIdx.x, tid = threadIdx.x;
    __shared__ int spos[TOPK];
    if (tid == 0) {
#pragma unroll
        for (int k = 0; k < TOPK; k++) {
            int e = g_tok_e[t * 2 + k];
            int p = g_off[e] + atomicAdd(&g_cur[e], 1);
            spos[k] = p;
            g_row_tok[p] = t;
            g_row_gate[p] = g_tok_g[t * 2 + k];
        }
    }
    __syncthreads();
    const float4* src = reinterpret_cast<const float4*>(X + (size_t)t * Dm);
#pragma unroll
    for (int k = 0; k < TOPK; k++) {
        float4* dst = reinterpret_cast<float4*>(g_XG + (size_t)spos[k] * Dm);
        dst[tid] = src[tid];
    }
}

__global__ void k_zero_mo()
{
    int t = blockIdx.x, tid = threadIdx.x;
    float4 z = make_float4(0.f, 0.f, 0.f, 0.f);
    reinterpret_cast<float4*>(g_MO + (size_t)t * Dm)[tid] = z;
}

__global__ void k_scatter()
{
    int p = blockIdx.x;
    int t = g_row_tok[p];
    if (t < 0) return;
    float gt = g_row_gate[p];
    int tid = threadIdx.x;
    for (int d = tid; d < Dm; d += 256)
        atomicAdd(&g_MO[(size_t)t * Dm + d], gt * g_YG[(size_t)p * Dm + d]);
}

__global__ void k_aux_final(float* __restrict__ out)
{
    int tid = threadIdx.x;
    float imp[Ee];
#pragma unroll
    for (int e = 0; e < Ee; e++) imp[e] = 0.f;
    for (int t = tid; t < Ntok; t += 256)
#pragma unroll
        for (int e = 0; e < Ee; e++) imp[e] += g_auxp[t * Ee + e];
    float ld[Ee];
#pragma unroll
    for (int e = 0; e < Ee; e++) ld[e] = 0.f;
    for (int i = tid; i < Ntok * TOPK; i += 256) ld[g_auxi[i]] += 1.f;

    __shared__ float red[256 * Ee];
    __shared__ float simp[Ee];
#pragma unroll
    for (int e = 0; e < Ee; e++) red[tid * Ee + e] = imp[e];
    __syncthreads();
    for (int st = 128; st > 0; st >>= 1) {
        if (tid < st)
#pragma unroll
            for (int e = 0; e < Ee; e++)
                red[tid * Ee + e] += red[(tid + st) * Ee + e];
        __syncthreads();
    }
    if (tid == 0)
#pragma unroll
        for (int e = 0; e < Ee; e++) simp[e] = red[e];
    __syncthreads();
#pragma unroll
    for (int e = 0; e < Ee; e++) red[tid * Ee + e] = ld[e];
    __syncthreads();
    for (int st = 128; st > 0; st >>= 1) {
        if (tid < st)
#pragma unroll
            for (int e = 0; e < Ee; e++)
                red[tid * Ee + e] += red[(tid + st) * Ee + e];
        __syncthreads();
    }
    if (tid == 0) {
        float aux = 0.f;
#pragma unroll
        for (int e = 0; e < Ee; e++)
            aux += (simp[e] / (float)Ntok) * (red[e] / (float)(Ntok * TOPK));
        out[0] = (float)Ee * aux;
    }
}

// ---------------- host orchestration ----------------
extern "C" void kernel_launch(void* const* d_in, const int* in_sizes, int n_in,
                              void* d_out, int out_size)
{
    (void)in_sizes; (void)n_in;
    const float* x     = (const float*)d_in[0];
    const float* enc   = (const float*)d_in[1];
    const float* sa_wq = (const float*)d_in[2];
    const float* sa_bq = (const float*)d_in[3];
    const float* sa_wk = (const float*)d_in[4];
    const float* sa_bk = (const float*)d_in[5];
    const float* sa_wv = (const float*)d_in[6];
    const float* sa_bv = (const float*)d_in[7];
    const float* sa_wo = (const float*)d_in[8];
    const float* sa_bo = (const float*)d_in[9];
    const float* ca_wq = (const float*)d_in[10];
    const float* ca_bq = (const float*)d_in[11];
    const float* ca_wk = (const float*)d_in[12];
    const float* ca_bk = (const float*)d_in[13];
    const float* ca_wv = (const float*)d_in[14];
    const float* ca_bv = (const float*)d_in[15];
    const float* ca_wo = (const float*)d_in[16];
    const float* ca_bo = (const float*)d_in[17];
    const float* n1_g  = (const float*)d_in[18];
    const float* n1_b  = (const float*)d_in[19];
    const float* n2_g  = (const float*)d_in[20];
    const float* n2_b  = (const float*)d_in[21];
    const float* n3_g  = (const float*)d_in[22];
    const float* n3_b  = (const float*)d_in[23];
    const float* r_w   = (const float*)d_in[24];
    const float* r_b   = (const float*)d_in[25];
    const float* e_w1  = (const float*)d_in[26];
    const float* e_b1  = (const float*)d_in[27];
    const float* e_w2  = (const float*)d_in[28];
    const float* e_b2  = (const float*)d_in[29];

    void *pQ, *pK, *pV, *pAT, *pPR, *pX1, *pX2, *pXG, *pHB, *pYG, *pMO;
    cudaGetSymbolAddress(&pQ,  g_Q);
    cudaGetSymbolAddress(&pK,  g_K);
    cudaGetSymbolAddress(&pV,  g_V);
    cudaGetSymbolAddress(&pAT, g_AT);
    cudaGetSymbolAddress(&pPR, g_PR);
    cudaGetSymbolAddress(&pX1, g_X1);
    cudaGetSymbolAddress(&pX2, g_X2);
    cudaGetSymbolAddress(&pXG, g_XG);
    cudaGetSymbolAddress(&pHB, g_HB);
    cudaGetSymbolAddress(&pYG, g_YG);
    cudaGetSymbolAddress(&pMO, g_MO);
    float* Q  = (float*)pQ;  float* K  = (float*)pK;  float* V  = (float*)pV;
    float* AT = (float*)pAT; float* PR = (float*)pPR;
    float* X1 = (float*)pX1; float* X2 = (float*)pX2;
    float* XG = (float*)pXG; float* HB = (float*)pHB; float* YG = (float*)pYG;
    float* out = (float*)d_out;

    static int smem_set = 0;
    if (!smem_set) {
        cudaFuncSetAttribute(k_flash, cudaFuncAttributeMaxDynamicSharedMemorySize, FLASH_SMEM);
        smem_set = 1;
    }

    dim3 blk(256);
    dim3 gProj(Ntok / 128, Dm / 128);
    dim3 gFlash(Sseq / QT, Bbat * Hh);

    // ---- self attention ----
    k_gemm128<<<gProj, blk>>>(x, Dm, sa_wq, Dm, sa_bq, Q, Dm, Ntok, Dm, 0);
    k_gemm128<<<gProj, blk>>>(x, Dm, sa_wk, Dm, sa_bk, K, Dm, Ntok, Dm, 0);
    k_gemm128<<<gProj, blk>>>(x, Dm, sa_wv, Dm, sa_bv, V, Dm, Ntok, Dm, 0);
    k_flash<<<gFlash, blk, FLASH_SMEM>>>(Q, K, V, AT);
    k_gemm128<<<gProj, blk>>>(AT, Dm, sa_wo, Dm, sa_bo, PR, Dm, Ntok, Dm, 0);
    k_ln_res<<<Ntok, blk>>>(x, PR, n1_g, n1_b, X1);

    // ---- cross attention ----
    k_gemm128<<<gProj, blk>>>(X1,  Dm, ca_wq, Dm, ca_bq, Q, Dm, Ntok, Dm, 0);
    k_gemm128<<<gProj, blk>>>(enc, Dm, ca_wk, Dm, ca_bk, K, Dm, Ntok, Dm, 0);
    k_gemm128<<<gProj, blk>>>(enc, Dm, ca_wv, Dm, ca_bv, V, Dm, Ntok, Dm, 0);
    k_flash<<<gFlash, blk, FLASH_SMEM>>>(Q, K, V, AT);
    k_gemm128<<<gProj, blk>>>(AT, Dm, ca_wo, Dm, ca_bo, PR, Dm, Ntok, Dm, 0);
    k_ln_res<<<Ntok, blk>>>(X1, PR, n2_g, n2_b, X2);

    // ---- MoE (sparse top-2 dispatch) ----
    k_moe_init<<<1, blk>>>();
    k_router<<<Ntok, blk>>>(X2, r_w, r_b, 0);
    k_offsets<<<1, 1>>>();
    k_gather<<<Ntok, blk>>>(X2);
    k_moe_gemm_mma<<<dim3(Ntok / 128, Ff / 128, Ee), blk>>>(XG, e_w1, e_b1, HB, Dm, Ff, 1);
    k_moe_gemm_mma<<<dim3(Ntok / 128, Dm / 128, Ee), blk>>>(HB, e_w2, e_b2, YG, Ff, Dm, 0);
    k_zero_mo<<<Ntok, blk>>>();
    k_scatter<<<NKCAP, blk>>>();
    k_ln_res<<<Ntok, blk>>>(X2, (float*)pMO, n3_g, n3_b, out);

    // ---- aux loss (router recompute on OUTPUT, per reference) ----
    if (out_size > Ntok * Dm) {
        k_router<<<Ntok, blk>>>(out, r_w, r_b, 1);
        k_aux_final<<<1, blk>>>(out + (out_size - 1));
    }
}